// round 14
// baseline (speedup 1.0000x reference)
#include <cuda_runtime.h>
#include <cuda_bf16.h>

// Problem constants (fixed by the reference setup_inputs)
#define BATCH   16
#define HW      512
#define MCOMP   200000
#define NBLK    74             // 74*16 = 1184 = 148 SMs * 8 blocks: one FULL wave
#define NTHR    256

#define EPS_F   1e-10f
#define THR_F   1.1f            // 1.0 + DELTA

// Scratch for per-block partial sums: (sum_w, sum_w*mismatch)
__device__ float2 g_part[BATCH * NBLK];

__device__ __forceinline__ void whdr_one(const float* __restrict__ img,
                                         const float2* __restrict__ c2,
                                         int m, float& ws, float& wm)
{
    const float2 p0 = c2[m * 3 + 0];   // (x1, y1)
    const float2 p1 = c2[m * 3 + 1];   // (x2, y2)
    const float2 p2 = c2[m * 3 + 2];   // (darker, weight)

    const int x1 = (int)p0.x, y1 = (int)p0.y;
    const int x2 = (int)p1.x, y2 = (int)p1.y;
    const int darker = (int)p2.x;
    const float w = p2.y;

    const float r1 = __ldg(img + y1 * HW + x1);
    const float r2 = __ldg(img + y2 * HW + x2);

    // alg = 1 if r2/(r1+eps) > thr ; 2 if r1/(r2+eps) > thr ; else 0
    // multiply-form (all values positive) avoids divides
    int alg = 0;
    if (r2 > THR_F * (r1 + EPS_F))      alg = 1;
    else if (r1 > THR_F * (r2 + EPS_F)) alg = 2;

    ws += w;
    if (alg != darker) wm += w;
}

// R2's proven mainloop, widened to a full resident wave (8 blocks/SM, 64 warps).
__global__ __launch_bounds__(NTHR, 8)
void whdr_partial_kernel(const float* __restrict__ v_input,
                         const float* __restrict__ comparisons,
                         const int*   __restrict__ numComparisons)
{
    const int b   = blockIdx.y;
    const int blk = blockIdx.x;
    const float* __restrict__ img = v_input + (size_t)b * HW * HW;
    const float2* __restrict__ c2 =
        (const float2*)(comparisons + (size_t)b * MCOMP * 6);
    const int n = numComparisons[b];

    float ws0 = 0.0f, wm0 = 0.0f;
    float ws1 = 0.0f, wm1 = 0.0f;

    const int stride = NBLK * NTHR;
    int m = blk * NTHR + threadIdx.x;
    for (; m + stride < n; m += 2 * stride) {
        whdr_one(img, c2, m,          ws0, wm0);
        whdr_one(img, c2, m + stride, ws1, wm1);
    }
    if (m < n) whdr_one(img, c2, m, ws0, wm0);

    float ws = ws0 + ws1;
    float wm = wm0 + wm1;

    // block reduction (8 warps)
    __shared__ float s_ws[NTHR / 32];
    __shared__ float s_wm[NTHR / 32];
    const int lane = threadIdx.x & 31;
    const int warp = threadIdx.x >> 5;
    #pragma unroll
    for (int o = 16; o > 0; o >>= 1) {
        ws += __shfl_down_sync(0xFFFFFFFFu, ws, o);
        wm += __shfl_down_sync(0xFFFFFFFFu, wm, o);
    }
    if (lane == 0) { s_ws[warp] = ws; s_wm[warp] = wm; }
    __syncthreads();
    if (warp == 0) {
        ws = (lane < NTHR / 32) ? s_ws[lane] : 0.0f;
        wm = (lane < NTHR / 32) ? s_wm[lane] : 0.0f;
        #pragma unroll
        for (int o = 4; o > 0; o >>= 1) {
            ws += __shfl_down_sync(0xFFFFFFFFu, ws, o);
            wm += __shfl_down_sync(0xFFFFFFFFu, wm, o);
        }
        if (lane == 0) g_part[b * NBLK + blk] = make_float2(ws, wm);
    }
}

// Final reduction with PDL: launched with programmaticStreamSerialization,
// begins ramp while the partial kernel drains; cudaGridDependencySynchronize
// blocks until the partial grid completes (memory visibility guaranteed).
__global__ __launch_bounds__(512)
void whdr_final_kernel(float* __restrict__ out)
{
#if __CUDA_ARCH__ >= 900
    cudaGridDependencySynchronize();
#endif

    const int warp = threadIdx.x >> 5;   // batch index, 0..15
    const int lane = threadIdx.x & 31;

    float ws = 0.0f, wm = 0.0f;
    #pragma unroll
    for (int k = lane; k < NBLK; k += 32) {   // 74 partials: 3 strided loads
        const float2 p = g_part[warp * NBLK + k];
        ws += p.x;
        wm += p.y;
    }
    #pragma unroll
    for (int o = 16; o > 0; o >>= 1) {
        ws += __shfl_down_sync(0xFFFFFFFFu, ws, o);
        wm += __shfl_down_sync(0xFFFFFFFFu, wm, o);
    }

    __shared__ float s_per[BATCH];
    if (lane == 0) s_per[warp] = wm / ws;
    __syncthreads();

    if (threadIdx.x == 0) {
        float s = 0.0f;
        #pragma unroll
        for (int i = 0; i < BATCH; i++) s += s_per[i];
        out[0] = s * (1.0f / BATCH);
    }
}

extern "C" void kernel_launch(void* const* d_in, const int* in_sizes, int n_in,
                              void* d_out, int out_size)
{
    const float* v_input        = (const float*)d_in[0];
    const float* comparisons    = (const float*)d_in[1];
    const int*   numComparisons = (const int*)  d_in[2];
    float* out = (float*)d_out;

    dim3 grid(NBLK, BATCH, 1);
    whdr_partial_kernel<<<grid, NTHR>>>(v_input, comparisons, numComparisons);

    // PDL launch of the final reduction (programmatic edge in the graph).
    cudaLaunchConfig_t cfg = {};
    cfg.gridDim  = dim3(1, 1, 1);
    cfg.blockDim = dim3(512, 1, 1);
    cfg.dynamicSmemBytes = 0;
    cfg.stream = 0;

    cudaLaunchAttribute attrs[1];
    attrs[0].id = cudaLaunchAttributeProgrammaticStreamSerialization;
    attrs[0].val.programmaticStreamSerializationAllowed = 1;
    cfg.attrs    = attrs;
    cfg.numAttrs = 1;

    cudaLaunchKernelEx(&cfg, whdr_final_kernel, out);
}